// round 13
// baseline (speedup 1.0000x reference)
#include <cuda_runtime.h>
#include <cuda_fp16.h>

// out[b,l,g,o] = sum_k mask(b,l,k) * sum_i X[b,l+k-2,g*64+i] * W[g,o,i,k]
// mask(l,k) = (pos[l+k-2]-(l+k-2) == pos[l]-l); X zero-padded outside [0,L).
// Single-pass fp16 (X,W rounded once), fp32 accumulate. rel_err ~3e-4.
// W pre-arranged in mma-fragment order; staged once per CTA into smem.
// TL=256 rows/CTA; 8 warps, each M=32 x N=64, B software-pipelined (dist 1).
// 256 thr/CTA, 2 CTAs/SM.

constexpr int Bb = 4, Ll = 4096, Cc = 1024, Gg = 16, IPG = 64, OPG = 64, KK = 5, TL = 256;
constexpr int A_ROWS = TL + 4;    // 260

// W in fragment order: uint = 2 halfs; index = ((((g*5+k)*4+q)*4+p)*32+L)*4+j
__device__ unsigned g_Wfrag[Gg * KK * 4 * 4 * 32 * 4];

// smem layout (bytes)
constexpr int SA   = 0;                        // A: 260 x 128B swizzled rows
constexpr int SW_F = A_ROWS * 128;             // 33280: W frags, 2560 x 16B linear
constexpr int W_BYTES = KK * 4 * 4 * 32 * 16;  // 40960
constexpr int S_DQ = SW_F + W_BYTES;           // 74240: dq, 260 ints
constexpr int SMEM_BYTES = S_DQ + A_ROWS * 4 + 16;   // ~75.3 KB -> 2 CTAs/SM

__device__ __forceinline__ unsigned smem_u32(const void* p) {
    unsigned a;
    asm("{ .reg .u64 t; cvta.to.shared.u64 t, %1; cvt.u32.u64 %0, t; }" : "=r"(a) : "l"(p));
    return a;
}
__device__ __forceinline__ unsigned sw128(unsigned off) { return off ^ ((off >> 3) & 0x70); }

__device__ __forceinline__ void sts64(unsigned addr, unsigned r0, unsigned r1) {
    asm volatile("st.shared.v2.b32 [%0], {%1, %2};" :: "r"(addr), "r"(r0), "r"(r1) : "memory");
}
__device__ __forceinline__ void ldsm4(unsigned addr, unsigned& r0, unsigned& r1,
                                      unsigned& r2, unsigned& r3) {
    asm volatile("ldmatrix.sync.aligned.m8n8.x4.shared.b16 {%0, %1, %2, %3}, [%4];"
                 : "=r"(r0), "=r"(r1), "=r"(r2), "=r"(r3) : "r"(addr));
}
__device__ __forceinline__ void lds128(unsigned addr, unsigned& r0, unsigned& r1,
                                       unsigned& r2, unsigned& r3) {
    asm volatile("ld.shared.v4.b32 {%0, %1, %2, %3}, [%4];"
                 : "=r"(r0), "=r"(r1), "=r"(r2), "=r"(r3) : "r"(addr));
}
__device__ __forceinline__ void mma16816(float* c,
                                         unsigned a0, unsigned a1, unsigned a2, unsigned a3,
                                         unsigned b0, unsigned b1) {
    asm volatile("mma.sync.aligned.m16n8k16.row.col.f32.f16.f16.f32 "
                 "{%0,%1,%2,%3}, {%4,%5,%6,%7}, {%8,%9}, {%0,%1,%2,%3};"
                 : "+f"(c[0]), "+f"(c[1]), "+f"(c[2]), "+f"(c[3])
                 : "r"(a0), "r"(a1), "r"(a2), "r"(a3), "r"(b0), "r"(b1));
}
__device__ __forceinline__ void cp16(unsigned dst, const void* src) {
    asm volatile("cp.async.cg.shared.global [%0], [%1], 16;" :: "r"(dst), "l"(src) : "memory");
}

// ---- pre-kernel: W (g,o,i,k) f32 -> fragment-ordered fp16 pairs ----
// reg j of lane L, tile (k,q,p):  o = p*16 + 8*(j>>1) + (L>>2)
//                                 i = q*16 + 8*(j&1) + 2*(L&3)   (+1 for hi half)
__global__ void prep_w(const float* __restrict__ w) {
    int idx = blockIdx.x * 256 + threadIdx.x;
    if (idx >= Gg * KK * 4 * 4 * 32 * 4) return;
    int j = idx & 3;
    int L = (idx >> 2) & 31;
    int p = (idx >> 7) & 3;
    int q = (idx >> 9) & 3;
    int rem = idx >> 11;
    int k = rem % KK;
    int g = rem / KK;
    int o = p * 16 + ((j >> 1) << 3) + (L >> 2);
    int i = q * 16 + ((j & 1) << 3) + ((L & 3) << 1);
    float v0 = w[(((g * OPG + o) * IPG + i) * KK) + k];
    float v1 = w[(((g * OPG + o) * IPG + i + 1) * KK) + k];
    unsigned pk;
    asm("cvt.rn.f16x2.f32 %0, %1, %2;" : "=r"(pk) : "f"(v1), "f"(v0));
    g_Wfrag[idx] = pk;
}

__global__ __launch_bounds__(256, 2)
void masked_conv1d_hmma(const float* __restrict__ x,
                        const int*   __restrict__ pos,
                        float*       __restrict__ out) {
    extern __shared__ char sm[];
    const unsigned smb = smem_u32(sm);
    const int l0 = blockIdx.x * TL, g = blockIdx.y, b = blockIdx.z;
    const int tid = threadIdx.x;
    const int wid = tid >> 5, lane = tid & 31;
    const int lane8 = lane & 7, seg = lane >> 3;

    // ---- stage ALL W fragments for this g into smem (2560 x 16B chunks) ----
    {
        const char* wsrc = (const char*)((const uint4*)g_Wfrag + (size_t)g * (KK * 16 * 32));
#pragma unroll
        for (int t = 0; t < 10; t++) {
            int ch = tid + t * 256;
            cp16(smb + SW_F + (unsigned)ch * 16, wsrc + (size_t)ch * 16);
        }
        asm volatile("cp.async.commit_group;" ::: "memory");
    }

    // ---- stage position deltas into smem (coalesced) ----
    int* dq = (int*)(sm + S_DQ);
    for (int j = tid; j < A_ROWS; j += 256) {
        int gl = l0 - 2 + j;
        dq[j] = (gl >= 0 && gl < Ll) ? (pos[b * Ll + gl] - gl) : (int)0x80000000 + j;
    }

    // ---- stage X tile: f32 -> fp16, swizzled 128B rows ----
    const float* xg = x + (size_t)b * Ll * Cc + g * IPG;
    for (int idx = tid; idx < A_ROWS * 16; idx += 256) {
        int j  = idx >> 4;
        int i4 = idx & 15;
        int gl = l0 - 2 + j;
        float4 v = make_float4(0.f, 0.f, 0.f, 0.f);
        if (gl >= 0 && gl < Ll)
            v = *(const float4*)(xg + (size_t)gl * Cc + i4 * 4);
        unsigned h0, h1;
        asm("cvt.rn.f16x2.f32 %0, %1, %2;" : "=r"(h0) : "f"(v.y), "f"(v.x));
        asm("cvt.rn.f16x2.f32 %0, %1, %2;" : "=r"(h1) : "f"(v.w), "f"(v.z));
        unsigned sw = sw128((unsigned)(j * 128 + i4 * 8));
        sts64(smb + SA + sw, h0, h1);
    }

    asm volatile("cp.async.wait_group 0;" ::: "memory");
    __syncthreads();                                  // A + dq + W visible; the ONLY barrier

    const int r0 = wid * 32 + (lane >> 2);            // warp owns rows [wid*32, wid*32+32)

    // ---- per-thread mask bits: bit(ci*5+k) = mask(row r0+ci*8, conv-k) ----
    unsigned mbits = 0;
#pragma unroll
    for (int ci = 0; ci < 4; ci++) {
        int cc = dq[r0 + ci * 8 + 2];
#pragma unroll
        for (int k = 0; k < KK; k++) {
            if (k == 2) continue;                     // mask(l,2) == 1 always
            if (dq[r0 + ci * 8 + k] == cc) mbits |= 1u << (ci * 5 + k);
        }
    }

    // ---- accumulators: [mt 0..1][nt 0..7][e 0..3] ----
    float c[2][8][4];
#pragma unroll
    for (int mt = 0; mt < 2; mt++)
#pragma unroll
        for (int nt = 0; nt < 8; nt++)
#pragma unroll
            for (int e = 0; e < 4; e++) c[mt][nt][e] = 0.f;

    const unsigned acoff = (unsigned)((seg >> 1) << 3);
    const unsigned wbase = smb + SW_F + (unsigned)lane * 16;   // per-lane W frag base

    // prefetch B for it=0 (4 blocks of 512B)
    unsigned bc[16];
    lds128(wbase,        bc[0],  bc[1],  bc[2],  bc[3]);
    lds128(wbase + 512,  bc[4],  bc[5],  bc[6],  bc[7]);
    lds128(wbase + 1024, bc[8],  bc[9],  bc[10], bc[11]);
    lds128(wbase + 1536, bc[12], bc[13], bc[14], bc[15]);

#pragma unroll
    for (int it = 0; it < 20; it++) {
        const int k = it >> 2, q = it & 3;

        // A fragments for this (k,q): two 16-row ldsm4 (M=32)
        unsigned ah[8];
        const unsigned arow = (unsigned)(wid * 32 + k + lane8 + ((seg & 1) << 3));
        unsigned a0 = smb + SA + sw128(arow * 128 + (q * 16 + acoff) * 2);
        unsigned a1 = smb + SA + sw128((arow + 16) * 128 + (q * 16 + acoff) * 2);
        ldsm4(a0, ah[0], ah[1], ah[2], ah[3]);
        ldsm4(a1, ah[4], ah[5], ah[6], ah[7]);

        if (k != 2) {                                 // center tap: mask == 1
            const bool m0 = (mbits >> (0 * 5 + k)) & 1;
            const bool m1 = (mbits >> (1 * 5 + k)) & 1;
            const bool m2 = (mbits >> (2 * 5 + k)) & 1;
            const bool m3 = (mbits >> (3 * 5 + k)) & 1;
            ah[0] = m0 ? ah[0] : 0u;  ah[2] = m0 ? ah[2] : 0u;
            ah[1] = m1 ? ah[1] : 0u;  ah[3] = m1 ? ah[3] : 0u;
            ah[4] = m2 ? ah[4] : 0u;  ah[6] = m2 ? ah[6] : 0u;
            ah[5] = m3 ? ah[5] : 0u;  ah[7] = m3 ? ah[7] : 0u;
        }

        // prefetch B for it+1 while MMAs of it run
        unsigned bn[16];
        if (it < 19) {
            unsigned wn = wbase + (unsigned)(it + 1) * 2048;
            lds128(wn,        bn[0],  bn[1],  bn[2],  bn[3]);
            lds128(wn + 512,  bn[4],  bn[5],  bn[6],  bn[7]);
            lds128(wn + 1024, bn[8],  bn[9],  bn[10], bn[11]);
            lds128(wn + 1536, bn[12], bn[13], bn[14], bn[15]);
        }

#pragma unroll
        for (int mt = 0; mt < 2; mt++) {
#pragma unroll
            for (int p = 0; p < 4; p++) {
                mma16816(c[mt][p*2],   ah[mt*4], ah[mt*4+1], ah[mt*4+2], ah[mt*4+3],
                         bc[p*4],   bc[p*4+1]);
                mma16816(c[mt][p*2+1], ah[mt*4], ah[mt*4+1], ah[mt*4+2], ah[mt*4+3],
                         bc[p*4+2], bc[p*4+3]);
            }
        }

#pragma unroll
        for (int j = 0; j < 16; j++) bc[j] = bn[j];
    }

    // ---- epilogue: fragments -> out (B,L,G,OPG) ----
    const int ocol = (lane & 3) * 2;
#pragma unroll
    for (int mt = 0; mt < 2; mt++) {
        const int row0 = l0 + wid * 32 + mt * 16 + (lane >> 2);
        float* o0 = out + (((size_t)b * Ll + row0) * Gg + g) * OPG + ocol;
        float* o1 = o0 + (size_t)8 * Gg * OPG;
#pragma unroll
        for (int nt = 0; nt < 8; nt++) {
            *(float2*)(o0 + nt * 8) = make_float2(c[mt][nt][0], c[mt][nt][1]);
            *(float2*)(o1 + nt * 8) = make_float2(c[mt][nt][2], c[mt][nt][3]);
        }
    }
}

extern "C" void kernel_launch(void* const* d_in, const int* in_sizes, int n_in,
                              void* d_out, int out_size) {
    const float* x   = (const float*)d_in[0];
    const int*   pos = (const int*)d_in[1];
    const float* w   = (const float*)d_in[2];
    float*       out = (float*)d_out;

    prep_w<<<(Gg * KK * 4 * 4 * 32 * 4 + 255) / 256, 256>>>(w);

    cudaFuncSetAttribute(masked_conv1d_hmma,
                         cudaFuncAttributeMaxDynamicSharedMemorySize, SMEM_BYTES);
    dim3 grid(Ll / TL, Gg, Bb);   // (16, 16, 4)
    masked_conv1d_hmma<<<grid, 256, SMEM_BYTES>>>(x, pos, out);
}

// round 14
// speedup vs baseline: 1.2100x; 1.2100x over previous
#include <cuda_runtime.h>
#include <cuda_fp16.h>

// out[b,l,g,o] = sum_k mask(b,l,k) * sum_i X[b,l+k-2,g*64+i] * W[g,o,i,k]
// mask(l,k) = (pos[l+k-2]-(l+k-2) == pos[l]-l); X zero-padded outside [0,L).
// Single-pass fp16 (X,W rounded once), fp32 accumulate. rel_err ~3e-4.
// W pre-arranged in mma-fragment order; staged once per CTA into smem.
// Warp tile M=32 x N=32; BOTH A and B software-pipelined at distance 1.
// 256 thr/CTA (8 warps: 4 M-tiles x 2 N-halves), 3 CTAs/SM (24 warps/SM).

constexpr int Bb = 4, Ll = 4096, Cc = 1024, Gg = 16, IPG = 64, OPG = 64, KK = 5, TL = 128;
constexpr int A_ROWS = TL + 4;    // 132

// W in fragment order: uint = 2 halfs; index = ((((g*5+k)*4+q)*4+p)*32+L)*4+j
__device__ unsigned g_Wfrag[Gg * KK * 4 * 4 * 32 * 4];

// smem layout (bytes)
constexpr int SA   = 0;                        // A: 132 x 128B swizzled rows
constexpr int SW_F = A_ROWS * 128;             // 16896: W frags, 2560 x 16B linear
constexpr int W_BYTES = KK * 4 * 4 * 32 * 16;  // 40960
constexpr int S_DQ = SW_F + W_BYTES;           // 57856: dq, 132 ints
constexpr int SMEM_BYTES = S_DQ + A_ROWS * 4 + 16;   // ~58.4 KB -> 3 CTAs/SM

__device__ __forceinline__ unsigned smem_u32(const void* p) {
    unsigned a;
    asm("{ .reg .u64 t; cvta.to.shared.u64 t, %1; cvt.u32.u64 %0, t; }" : "=r"(a) : "l"(p));
    return a;
}
__device__ __forceinline__ unsigned sw128(unsigned off) { return off ^ ((off >> 3) & 0x70); }

__device__ __forceinline__ void sts64(unsigned addr, unsigned r0, unsigned r1) {
    asm volatile("st.shared.v2.b32 [%0], {%1, %2};" :: "r"(addr), "r"(r0), "r"(r1) : "memory");
}
__device__ __forceinline__ void ldsm4(unsigned addr, unsigned& r0, unsigned& r1,
                                      unsigned& r2, unsigned& r3) {
    asm volatile("ldmatrix.sync.aligned.m8n8.x4.shared.b16 {%0, %1, %2, %3}, [%4];"
                 : "=r"(r0), "=r"(r1), "=r"(r2), "=r"(r3) : "r"(addr));
}
__device__ __forceinline__ void lds128(unsigned addr, unsigned& r0, unsigned& r1,
                                       unsigned& r2, unsigned& r3) {
    asm volatile("ld.shared.v4.b32 {%0, %1, %2, %3}, [%4];"
                 : "=r"(r0), "=r"(r1), "=r"(r2), "=r"(r3) : "r"(addr));
}
__device__ __forceinline__ void mma16816(float* c,
                                         unsigned a0, unsigned a1, unsigned a2, unsigned a3,
                                         unsigned b0, unsigned b1) {
    asm volatile("mma.sync.aligned.m16n8k16.row.col.f32.f16.f16.f32 "
                 "{%0,%1,%2,%3}, {%4,%5,%6,%7}, {%8,%9}, {%0,%1,%2,%3};"
                 : "+f"(c[0]), "+f"(c[1]), "+f"(c[2]), "+f"(c[3])
                 : "r"(a0), "r"(a1), "r"(a2), "r"(a3), "r"(b0), "r"(b1));
}
__device__ __forceinline__ void cp16(unsigned dst, const void* src) {
    asm volatile("cp.async.cg.shared.global [%0], [%1], 16;" :: "r"(dst), "l"(src) : "memory");
}

// ---- pre-kernel: W (g,o,i,k) f32 -> fragment-ordered fp16 pairs ----
// reg j of lane L, tile (k,q,p):  o = p*16 + 8*(j>>1) + (L>>2)
//                                 i = q*16 + 8*(j&1) + 2*(L&3)   (+1 for hi half)
__global__ void prep_w(const float* __restrict__ w) {
    int idx = blockIdx.x * 256 + threadIdx.x;
    if (idx >= Gg * KK * 4 * 4 * 32 * 4) return;
    int j = idx & 3;
    int L = (idx >> 2) & 31;
    int p = (idx >> 7) & 3;
    int q = (idx >> 9) & 3;
    int rem = idx >> 11;
    int k = rem % KK;
    int g = rem / KK;
    int o = p * 16 + ((j >> 1) << 3) + (L >> 2);
    int i = q * 16 + ((j & 1) << 3) + ((L & 3) << 1);
    float v0 = w[(((g * OPG + o) * IPG + i) * KK) + k];
    float v1 = w[(((g * OPG + o) * IPG + i + 1) * KK) + k];
    unsigned pk;
    asm("cvt.rn.f16x2.f32 %0, %1, %2;" : "=r"(pk) : "f"(v1), "f"(v0));
    g_Wfrag[idx] = pk;
}

__global__ __launch_bounds__(256, 3)
void masked_conv1d_hmma(const float* __restrict__ x,
                        const int*   __restrict__ pos,
                        float*       __restrict__ out) {
    extern __shared__ char sm[];
    const unsigned smb = smem_u32(sm);
    const int l0 = blockIdx.x * TL, g = blockIdx.y, b = blockIdx.z;
    const int tid = threadIdx.x;
    const int wid = tid >> 5, lane = tid & 31;
    const int lane8 = lane & 7, seg = lane >> 3;

    // ---- stage ALL W fragments for this g into smem (2560 x 16B chunks) ----
    {
        const char* wsrc = (const char*)((const uint4*)g_Wfrag + (size_t)g * (KK * 16 * 32));
#pragma unroll
        for (int t = 0; t < 10; t++) {
            int ch = tid + t * 256;
            cp16(smb + SW_F + (unsigned)ch * 16, wsrc + (size_t)ch * 16);
        }
        asm volatile("cp.async.commit_group;" ::: "memory");
    }

    // ---- stage position deltas into smem (coalesced) ----
    int* dq = (int*)(sm + S_DQ);
    for (int j = tid; j < A_ROWS; j += 256) {
        int gl = l0 - 2 + j;
        dq[j] = (gl >= 0 && gl < Ll) ? (pos[b * Ll + gl] - gl) : (int)0x80000000 + j;
    }

    // ---- stage X tile: f32 -> fp16, swizzled 128B rows ----
    const float* xg = x + (size_t)b * Ll * Cc + g * IPG;
    for (int idx = tid; idx < A_ROWS * 16; idx += 256) {
        int j  = idx >> 4;
        int i4 = idx & 15;
        int gl = l0 - 2 + j;
        float4 v = make_float4(0.f, 0.f, 0.f, 0.f);
        if (gl >= 0 && gl < Ll)
            v = *(const float4*)(xg + (size_t)gl * Cc + i4 * 4);
        unsigned h0, h1;
        asm("cvt.rn.f16x2.f32 %0, %1, %2;" : "=r"(h0) : "f"(v.y), "f"(v.x));
        asm("cvt.rn.f16x2.f32 %0, %1, %2;" : "=r"(h1) : "f"(v.w), "f"(v.z));
        unsigned sw = sw128((unsigned)(j * 128 + i4 * 8));
        sts64(smb + SA + sw, h0, h1);
    }

    asm volatile("cp.async.wait_group 0;" ::: "memory");
    __syncthreads();                                  // A + dq + W visible; the ONLY barrier

    const int mw = wid >> 1;          // 0..3: M-tile (32 rows)
    const int nw = wid & 1;           // 0..1: N-half (32 cols)
    const int r0 = mw * 32 + (lane >> 2);

    // ---- per-thread mask bits: bit(ci*5+k) = mask(row r0+ci*8, conv-k) ----
    unsigned mbits = 0;
#pragma unroll
    for (int ci = 0; ci < 4; ci++) {
        int cc = dq[r0 + ci * 8 + 2];
#pragma unroll
        for (int k = 0; k < KK; k++) {
            if (k == 2) continue;                     // mask(l,2) == 1 always
            if (dq[r0 + ci * 8 + k] == cc) mbits |= 1u << (ci * 5 + k);
        }
    }

    // ---- accumulators: [mt 0..1][nt 0..3][e 0..3] ----
    float c[2][4][4];
#pragma unroll
    for (int mt = 0; mt < 2; mt++)
#pragma unroll
        for (int nt = 0; nt < 4; nt++)
#pragma unroll
            for (int e = 0; e < 4; e++) c[mt][nt][e] = 0.f;

    const unsigned acoff = (unsigned)((seg >> 1) << 3);
    // per-lane W base for this warp's N-half
    const unsigned wbase = smb + SW_F + (unsigned)(nw * 2) * 512 + (unsigned)lane * 16;

    // ---- prologue: prefetch A and B for it=0 ----
    unsigned bc[8], ah[8];
    lds128(wbase,       bc[0], bc[1], bc[2], bc[3]);
    lds128(wbase + 512, bc[4], bc[5], bc[6], bc[7]);
    {
        const unsigned arow = (unsigned)(mw * 32 + 0 + lane8 + ((seg & 1) << 3));
        unsigned a0 = smb + SA + sw128(arow * 128 + (0 * 16 + acoff) * 2);
        unsigned a1 = smb + SA + sw128((arow + 16) * 128 + (0 * 16 + acoff) * 2);
        ldsm4(a0, ah[0], ah[1], ah[2], ah[3]);
        ldsm4(a1, ah[4], ah[5], ah[6], ah[7]);
    }

#pragma unroll
    for (int it = 0; it < 20; it++) {
        const int k = it >> 2;

        // prefetch A and B for it+1 while MMAs of it run
        unsigned bn[8], an[8];
        if (it < 19) {
            unsigned wn = wbase + (unsigned)(it + 1) * 2048;
            lds128(wn,       bn[0], bn[1], bn[2], bn[3]);
            lds128(wn + 512, bn[4], bn[5], bn[6], bn[7]);
            const int kn = (it + 1) >> 2, qn = (it + 1) & 3;
            const unsigned arown = (unsigned)(mw * 32 + kn + lane8 + ((seg & 1) << 3));
            unsigned a0 = smb + SA + sw128(arown * 128 + (qn * 16 + acoff) * 2);
            unsigned a1 = smb + SA + sw128((arown + 16) * 128 + (qn * 16 + acoff) * 2);
            ldsm4(a0, an[0], an[1], an[2], an[3]);
            ldsm4(a1, an[4], an[5], an[6], an[7]);
        }

        // row-granular mask on current A fragments (center tap k=2 is all-ones)
        if (k != 2) {
            const bool m0 = (mbits >> (0 * 5 + k)) & 1;
            const bool m1 = (mbits >> (1 * 5 + k)) & 1;
            const bool m2 = (mbits >> (2 * 5 + k)) & 1;
            const bool m3 = (mbits >> (3 * 5 + k)) & 1;
            ah[0] = m0 ? ah[0] : 0u;  ah[2] = m0 ? ah[2] : 0u;
            ah[1] = m1 ? ah[1] : 0u;  ah[3] = m1 ? ah[3] : 0u;
            ah[4] = m2 ? ah[4] : 0u;  ah[6] = m2 ? ah[6] : 0u;
            ah[5] = m3 ? ah[5] : 0u;  ah[7] = m3 ? ah[7] : 0u;
        }

#pragma unroll
        for (int mt = 0; mt < 2; mt++) {
            mma16816(c[mt][0], ah[mt*4], ah[mt*4+1], ah[mt*4+2], ah[mt*4+3], bc[0], bc[1]);
            mma16816(c[mt][1], ah[mt*4], ah[mt*4+1], ah[mt*4+2], ah[mt*4+3], bc[2], bc[3]);
            mma16816(c[mt][2], ah[mt*4], ah[mt*4+1], ah[mt*4+2], ah[mt*4+3], bc[4], bc[5]);
            mma16816(c[mt][3], ah[mt*4], ah[mt*4+1], ah[mt*4+2], ah[mt*4+3], bc[6], bc[7]);
        }

#pragma unroll
        for (int j = 0; j < 8; j++) { bc[j] = bn[j]; ah[j] = an[j]; }
    }

    // ---- epilogue: fragments -> out (B,L,G,OPG) ----
    const int ocol = nw * 32 + (lane & 3) * 2;
#pragma unroll
    for (int mt = 0; mt < 2; mt++) {
        const int row0 = l0 + mw * 32 + mt * 16 + (lane >> 2);
        float* o0 = out + (((size_t)b * Ll + row0) * Gg + g) * OPG + ocol;
        float* o1 = o0 + (size_t)8 * Gg * OPG;
#pragma unroll
        for (int nt = 0; nt < 4; nt++) {
            *(float2*)(o0 + nt * 8) = make_float2(c[mt][nt][0], c[mt][nt][1]);
            *(float2*)(o1 + nt * 8) = make_float2(c[mt][nt][2], c[mt][nt][3]);
        }
    }
}

extern "C" void kernel_launch(void* const* d_in, const int* in_sizes, int n_in,
                              void* d_out, int out_size) {
    const float* x   = (const float*)d_in[0];
    const int*   pos = (const int*)d_in[1];
    const float* w   = (const float*)d_in[2];
    float*       out = (float*)d_out;

    prep_w<<<(Gg * KK * 4 * 4 * 32 * 4 + 255) / 256, 256>>>(w);

    cudaFuncSetAttribute(masked_conv1d_hmma,
                         cudaFuncAttributeMaxDynamicSharedMemorySize, SMEM_BYTES);
    dim3 grid(Ll / TL, Gg, Bb);   // (32, 16, 4)
    masked_conv1d_hmma<<<grid, 256, SMEM_BYTES>>>(x, pos, out);
}